// round 8
// baseline (speedup 1.0000x reference)
#include <cuda_runtime.h>

#define NN 8192
#define NE 32768
#define NB 32
#define EB 1024

// ---------------- device scratch (no allocations allowed) ----------------
__device__ int   g_is64;
__device__ int   g_src[NE], g_dst[NE];
__device__ int   g_cnt[NN];
__device__ int   g_start[NN + 1];
__device__ float g_cntf[NN];
__device__ int   g_bhist[NB * NN];
__device__ int   g_perm[NE];
__device__ float g_m[147 * NE];            // m1_aug(33)|m2_aug(49)|m3_aug(65), column-major [k][e]
__device__ float g_W[80 * 3200];           // Wcat for current conv
__device__ float g_Q[(size_t)NN * 3200];   // Q = h @ Wcat (max ~105 MB)
__device__ float g_msg[NE * 64];
__device__ float g_h1[NN * 80];
__device__ float g_h2[NN * 80];
__device__ float g_d3[NN * 16];
__device__ float g_gum[NN * 16];

__device__ __forceinline__ float lrelu(float v) { return v >= 0.f ? v : 0.01f * v; }

// ---------------- packed fp32x2 helpers (Blackwell FFMA2 via PTX) ----------------
__device__ __forceinline__ unsigned long long pk2(float lo, float hi) {
    unsigned long long r;
    asm("mov.b64 %0, {%1, %2};" : "=l"(r) : "f"(lo), "f"(hi));
    return r;
}
__device__ __forceinline__ void ffma2(unsigned long long& d, unsigned long long a, unsigned long long b) {
    asm("fma.rn.f32x2 %0, %1, %2, %0;" : "+l"(d) : "l"(a), "l"(b));
}
__device__ __forceinline__ float2 upk2(unsigned long long v) {
    float2 f;
    asm("mov.b64 {%0, %1}, %2;" : "=f"(f.x), "=f"(f.y) : "l"(v));
    return f;
}

// ---------------- edge_index dtype detection + conversion ----------------
__global__ void detect_k(const void* ei) {
    if (threadIdx.x == 0) {
        const long long* p = (const long long*)ei;
        int ok = 1;
        for (int i = 0; i < 64; i++) {
            long long v = p[i];
            if (v < 0 || v >= NN) ok = 0;
        }
        g_is64 = ok;
    }
}

__global__ void convert_k(const void* ei) {
    int e = blockIdx.x * 256 + threadIdx.x;
    if (e >= NE) return;
    if (g_is64) {
        const long long* p = (const long long*)ei;
        g_src[e] = (int)p[e];
        g_dst[e] = (int)p[NE + e];
    } else {
        const int* p = (const int*)ei;
        g_src[e] = p[e];
        g_dst[e] = p[NE + e];
    }
}

// ---------------- deterministic dst-CSR build ----------------
__global__ void zero_cnt_k() { g_cnt[blockIdx.x * 256 + threadIdx.x] = 0; }

__global__ void hist_k() {
    int e = blockIdx.x * 256 + threadIdx.x;
    atomicAdd(&g_cnt[g_dst[e]], 1);
}

__global__ __launch_bounds__(1024) void scan_k() {
    __shared__ int ps[1024];
    int t = threadIdx.x;
    int loc[8];
    int s = 0;
    for (int i = 0; i < 8; i++) { loc[i] = g_cnt[t * 8 + i]; s += loc[i]; }
    ps[t] = s;
    __syncthreads();
    for (int d = 1; d < 1024; d <<= 1) {
        int v = (t >= d) ? ps[t - d] : 0;
        __syncthreads();
        ps[t] += v;
        __syncthreads();
    }
    int run = (t > 0) ? ps[t - 1] : 0;
    for (int i = 0; i < 8; i++) {
        int n = t * 8 + i;
        g_start[n] = run;
        g_cntf[n]  = (float)(loc[i] > 1 ? loc[i] : 1);
        run += loc[i];
    }
    if (t == 1023) g_start[NN] = run;
}

__global__ __launch_bounds__(1024) void bhist_k() {
    __shared__ int h[NN];
    int t = threadIdx.x;
    for (int i = t; i < NN; i += 1024) h[i] = 0;
    __syncthreads();
    atomicAdd(&h[g_dst[blockIdx.x * EB + t]], 1);
    __syncthreads();
    for (int i = t; i < NN; i += 1024) g_bhist[blockIdx.x * NN + i] = h[i];
}

__global__ void colscan_k() {
    int n = blockIdx.x * 256 + threadIdx.x;
    if (n >= NN) return;
    int run = g_start[n];
#pragma unroll
    for (int b = 0; b < NB; b++) {
        int t = g_bhist[b * NN + n];
        g_bhist[b * NN + n] = run;
        run += t;
    }
}

__global__ __launch_bounds__(1024) void place_k() {
    __shared__ int d[EB];
    int t = threadIdx.x;
    int e = blockIdx.x * EB + t;
    d[t] = g_dst[e];
    __syncthreads();
    int myd = d[t];
    int rank = 0;
    for (int j = 0; j < EB; j++) {
        int v = d[j];
        if (j < t && v == myd) rank++;
    }
    g_perm[g_bhist[blockIdx.x * NN + myd] + rank] = e;
}

// ---------------- edge MLP layer 1 (all three convs) ----------------
__global__ __launch_bounds__(256) void edge_mlp_k(
    const float* __restrict__ ea,
    const float* __restrict__ w1a, const float* __restrict__ b1a,
    const float* __restrict__ w2a, const float* __restrict__ b2a,
    const float* __restrict__ w3a, const float* __restrict__ b3a)
{
    __shared__ float sw[2448];
    for (int i = threadIdx.x; i < 2448; i += 256) {
        float v;
        if      (i < 512)  v = w1a[i];
        else if (i < 544)  v = b1a[i - 512];
        else if (i < 1312) v = w2a[i - 544];
        else if (i < 1360) v = b2a[i - 1312];
        else if (i < 2384) v = w3a[i - 1360];
        else               v = b3a[i - 2384];
        sw[i] = v;
    }
    __syncthreads();
    int e = blockIdx.x * 256 + threadIdx.x;
    float a[16];
    const float4* ep = (const float4*)(ea + (size_t)e * 16);
    float4 q0 = ep[0], q1 = ep[1], q2 = ep[2], q3 = ep[3];
    a[0]=q0.x; a[1]=q0.y; a[2]=q0.z; a[3]=q0.w;
    a[4]=q1.x; a[5]=q1.y; a[6]=q1.z; a[7]=q1.w;
    a[8]=q2.x; a[9]=q2.y; a[10]=q2.z; a[11]=q2.w;
    a[12]=q3.x; a[13]=q3.y; a[14]=q3.z; a[15]=q3.w;

    for (int j = 0; j < 32; j++) {
        float s = sw[512 + j];
#pragma unroll
        for (int i = 0; i < 16; i++) s = fmaf(a[i], sw[i * 32 + j], s);
        g_m[(size_t)j * NE + e] = lrelu(s);
    }
    g_m[(size_t)32 * NE + e] = 1.0f;

    for (int j = 0; j < 48; j++) {
        float s = sw[1312 + j];
#pragma unroll
        for (int i = 0; i < 16; i++) s = fmaf(a[i], sw[544 + i * 48 + j], s);
        g_m[(size_t)(33 + j) * NE + e] = lrelu(s);
    }
    g_m[(size_t)81 * NE + e] = 1.0f;

    for (int j = 0; j < 64; j++) {
        float s = sw[2384 + j];
#pragma unroll
        for (int i = 0; i < 16; i++) s = fmaf(a[i], sw[1360 + i * 64 + j], s);
        g_m[(size_t)(82 + j) * NE + e] = lrelu(s);
    }
    g_m[(size_t)146 * NE + e] = 1.0f;
}

// ---------------- Wcat = [wb blocks | bias block | root block] ----------------
__global__ void build_wcat_k(const float* __restrict__ wb, const float* __restrict__ bb,
                             const float* __restrict__ root, int inC, int K, int OUT)
{
    int idx = blockIdx.x * 256 + threadIdx.x;
    int Cc = (K + 2) * OUT;
    if (idx >= inC * Cc) return;
    int i = idx / Cc, c = idx - i * Cc;
    int k = c / OUT, o = c - k * OUT;
    float v;
    if (k < K)       v = wb[(size_t)k * inC * OUT + i * OUT + o];
    else if (k == K) v = bb[i * OUT + o];
    else             v = root[i * OUT + o];
    g_W[idx] = v;
}

// ---------------- SGEMM (packed FFMA2): g_Q[8192 x Cc] = A[8192 x Kd] @ g_W[Kd x Cc] ----
__global__ __launch_bounds__(256) void sgemm_k(const float* __restrict__ A, int Kd, int Cc)
{
    __shared__ float As[16][136];   // stride 136 floats = 544B (16B-aligned rows)
    __shared__ float Bs[16][128];
    int tid = threadIdx.x;
    int brow = blockIdx.y * 128;
    int bcol = blockIdx.x * 128;
    int tr = tid >> 4, tc = tid & 15;

    unsigned long long acc2[8][4];  // 8 rows x 4 packed col-pairs
#pragma unroll
    for (int i = 0; i < 8; i++)
#pragma unroll
        for (int j = 0; j < 4; j++) acc2[i][j] = 0ull;

    for (int k0 = 0; k0 < Kd; k0 += 16) {
#pragma unroll
        for (int i = 0; i < 8; i++) {
            int idx = tid + i * 256;
            int m = idx >> 4, kk = idx & 15;
            As[kk][m] = A[(size_t)(brow + m) * Kd + k0 + kk];
        }
#pragma unroll
        for (int i = 0; i < 8; i++) {
            int idx = tid + i * 256;
            int kk = idx >> 7, c = idx & 127;
            int col = bcol + c;
            Bs[kk][c] = (col < Cc) ? g_W[(size_t)(k0 + kk) * Cc + col] : 0.f;
        }
        __syncthreads();
#pragma unroll
        for (int kk = 0; kk < 16; kk++) {
            float4 a0 = *(const float4*)&As[kk][tr * 8];
            float4 a1 = *(const float4*)&As[kk][tr * 8 + 4];
            const unsigned long long* brw = (const unsigned long long*)&Bs[kk][tc * 8];
            unsigned long long b2[4];
            b2[0] = brw[0]; b2[1] = brw[1]; b2[2] = brw[2]; b2[3] = brw[3];
            unsigned long long a2[8];
            a2[0] = pk2(a0.x, a0.x); a2[1] = pk2(a0.y, a0.y);
            a2[2] = pk2(a0.z, a0.z); a2[3] = pk2(a0.w, a0.w);
            a2[4] = pk2(a1.x, a1.x); a2[5] = pk2(a1.y, a1.y);
            a2[6] = pk2(a1.z, a1.z); a2[7] = pk2(a1.w, a1.w);
#pragma unroll
            for (int i = 0; i < 8; i++)
#pragma unroll
                for (int j = 0; j < 4; j++)
                    ffma2(acc2[i][j], a2[i], b2[j]);
        }
        __syncthreads();
    }
#pragma unroll
    for (int i = 0; i < 8; i++) {
        int row = brow + tr * 8 + i;
        int col0 = bcol + tc * 8;
        float2 c0 = upk2(acc2[i][0]);
        float2 c1 = upk2(acc2[i][1]);
        float2 c2 = upk2(acc2[i][2]);
        float2 c3 = upk2(acc2[i][3]);
        if (col0 + 3 < Cc)
            *(float4*)&g_Q[(size_t)row * Cc + col0] = make_float4(c0.x, c0.y, c1.x, c1.y);
        if (col0 + 7 < Cc)
            *(float4*)&g_Q[(size_t)row * Cc + col0 + 4] = make_float4(c2.x, c2.y, c3.x, c3.y);
    }
}

// ---------------- per-edge message ----------------
__global__ __launch_bounds__(256) void edge_msg64_k(int Cc, int Kp1, int mOff)
{
    int t = blockIdx.x * 256 + threadIdx.x;
    int e = t >> 6, o = t & 63;
    const float* mp = g_m + mOff + e;
    const float* q = g_Q + (size_t)g_src[e] * Cc + o;
    float acc = 0.f;
#pragma unroll 4
    for (int k = 0; k < Kp1; k++)
        acc = fmaf(__ldg(mp + (size_t)k * NE), __ldg(q + (size_t)k * 64), acc);
    g_msg[t] = acc;
}

__global__ __launch_bounds__(256) void edge_msg16_k(int Cc, int Kp1, int mOff)
{
    int t = blockIdx.x * 256 + threadIdx.x;
    int e = t >> 4, o = t & 15;
    const float* mp = g_m + mOff + e;
    const float* q = g_Q + (size_t)g_src[e] * Cc + o;
    float acc = 0.f;
#pragma unroll 4
    for (int k = 0; k < Kp1; k++)
        acc = fmaf(__ldg(mp + (size_t)k * NE), __ldg(q + (size_t)k * 16), acc);
    g_msg[t] = acc;
}

// ---------------- scatter-mean + root + bias + lrelu (+concat x) ----------------
__global__ __launch_bounds__(256) void agg64_k(int Cc, int rootCol,
    const float* __restrict__ bias, const float* __restrict__ x, float* __restrict__ hout)
{
    int gt = blockIdx.x * 256 + threadIdx.x;
    int node = gt >> 5, lane = gt & 31;
    int s = g_start[node], en = g_start[node + 1];
    float a0 = 0.f, a1 = 0.f;
    for (int j = s; j < en; j++) {
        int e = g_perm[j];
        const float* mr = g_msg + (size_t)e * 64;
        a0 += mr[lane];
        a1 += mr[lane + 32];
    }
    float cf = g_cntf[node];
    const float* qr = g_Q + (size_t)node * Cc + rootCol;
    hout[node * 80 + lane]      = lrelu(a0 / cf + qr[lane] + bias[lane]);
    hout[node * 80 + lane + 32] = lrelu(a1 / cf + qr[lane + 32] + bias[lane + 32]);
    if (lane < 16) hout[node * 80 + 64 + lane] = x[node * 16 + lane];
}

__global__ __launch_bounds__(256) void agg16_k(int Cc, int rootCol, const float* __restrict__ bias)
{
    int gt = blockIdx.x * 256 + threadIdx.x;
    int node = gt >> 4, lane = gt & 15;
    if (node >= NN) return;
    int s = g_start[node], en = g_start[node + 1];
    float a = 0.f;
    for (int j = s; j < en; j++)
        a += g_msg[(size_t)g_perm[j] * 16 + lane];
    g_d3[node * 16 + lane] =
        lrelu(a / g_cntf[node] + g_Q[(size_t)node * Cc + rootCol + lane] + bias[lane]);
}

// ---------------- JAX threefry2x32, PARTITIONABLE mode, bit_width=32 -----------
// bits[i] = out0 ^ out1 of threefry2x32((0,42), hi=0, lo=i)
__device__ __forceinline__ unsigned threefry_xor(unsigned x0, unsigned x1)
{
    const unsigned ks0 = 0u, ks1 = 42u, ks2 = 0u ^ 42u ^ 0x1BD11BDAu;
    unsigned v0 = x0 + ks0, v1 = x1 + ks1;
#define TFR(d) { v0 += v1; v1 = (v1 << d) | (v1 >> (32 - d)); v1 ^= v0; }
    TFR(13) TFR(15) TFR(26) TFR(6)   v0 += ks1; v1 += ks2 + 1u;
    TFR(17) TFR(29) TFR(16) TFR(24)  v0 += ks2; v1 += ks0 + 2u;
    TFR(13) TFR(15) TFR(26) TFR(6)   v0 += ks0; v1 += ks1 + 3u;
    TFR(17) TFR(29) TFR(16) TFR(24)  v0 += ks1; v1 += ks2 + 4u;
    TFR(13) TFR(15) TFR(26) TFR(6)   v0 += ks2; v1 += ks0 + 5u;
#undef TFR
    return v0 ^ v1;
}

__device__ __forceinline__ float bits_to_gumbel(unsigned b)
{
    float f = __uint_as_float((b >> 9) | 0x3F800000u) - 1.0f;  // [0,1)
    const float tiny = __uint_as_float(0x00800000u);           // FLT_MIN (normal)
    float u = fmaxf(f * 1.0f + tiny, tiny);                    // (1-tiny) rounds to 1.0f
    return -logf(-logf(u));
}

__global__ void gumbel_k()
{
    int i = blockIdx.x * 256 + threadIdx.x;   // 131072 elements, one each
    g_gum[i] = bits_to_gumbel(threefry_xor(0u, (unsigned)i));
}

// ---------------- final: one-hot(argmin(d3 + g)) ----------------
__global__ void out_k(float* __restrict__ out)
{
    int n = blockIdx.x * 256 + threadIdx.x;
    if (n >= NN) return;
    const float* d = g_d3 + n * 16;
    const float* g = g_gum + n * 16;
    float best = d[0] + g[0];
    int bi = 0;
#pragma unroll
    for (int c = 1; c < 16; c++) {
        float z = d[c] + g[c];
        if (z < best) { best = z; bi = c; }
    }
#pragma unroll
    for (int c = 0; c < 16; c++) out[n * 16 + c] = (c == bi) ? 1.0f : 0.0f;
}

// ---------------- host launch ----------------
extern "C" void kernel_launch(void* const* d_in, const int* in_sizes, int n_in,
                              void* d_out, int out_size)
{
    (void)in_sizes; (void)n_in; (void)out_size;
    const float* x     = (const float*)d_in[0];
    const void*  ei    = d_in[1];
    const float* ea    = (const float*)d_in[2];
    const float* w1a   = (const float*)d_in[3];
    const float* b1a   = (const float*)d_in[4];
    const float* w1b   = (const float*)d_in[5];
    const float* b1b   = (const float*)d_in[6];
    const float* root1 = (const float*)d_in[7];
    const float* bias1 = (const float*)d_in[8];
    const float* w2a   = (const float*)d_in[9];
    const float* b2a   = (const float*)d_in[10];
    const float* w2b   = (const float*)d_in[11];
    const float* b2b   = (const float*)d_in[12];
    const float* root2 = (const float*)d_in[13];
    const float* bias2 = (const float*)d_in[14];
    const float* w3a   = (const float*)d_in[15];
    const float* b3a   = (const float*)d_in[16];
    const float* w3b   = (const float*)d_in[17];
    const float* b3b   = (const float*)d_in[18];
    const float* root3 = (const float*)d_in[19];
    const float* bias3 = (const float*)d_in[20];
    float* out = (float*)d_out;

    float *h1, *h2;
    cudaGetSymbolAddress((void**)&h1, g_h1);
    cudaGetSymbolAddress((void**)&h2, g_h2);

    detect_k<<<1, 32>>>(ei);
    convert_k<<<NE / 256, 256>>>(ei);
    zero_cnt_k<<<NN / 256, 256>>>();
    hist_k<<<NE / 256, 256>>>();
    scan_k<<<1, 1024>>>();
    bhist_k<<<NB, 1024>>>();
    colscan_k<<<NN / 256, 256>>>();
    place_k<<<NB, 1024>>>();

    edge_mlp_k<<<NE / 256, 256>>>(ea, w1a, b1a, w2a, b2a, w3a, b3a);
    gumbel_k<<<131072 / 256, 256>>>();

    // conv1: in=16, K=32, OUT=64, Cc=34*64=2176
    build_wcat_k<<<(16 * 2176 + 255) / 256, 256>>>(w1b, b1b, root1, 16, 32, 64);
    sgemm_k<<<dim3(17, 64), 256>>>(x, 16, 2176);
    edge_msg64_k<<<NE * 64 / 256, 256>>>(2176, 33, 0);
    agg64_k<<<NN * 32 / 256, 256>>>(2176, 33 * 64, bias1, x, h1);

    // conv2: in=80, K=48, OUT=64, Cc=50*64=3200
    build_wcat_k<<<(80 * 3200 + 255) / 256, 256>>>(w2b, b2b, root2, 80, 48, 64);
    sgemm_k<<<dim3(25, 64), 256>>>(h1, 80, 3200);
    edge_msg64_k<<<NE * 64 / 256, 256>>>(3200, 49, 33 * NE);
    agg64_k<<<NN * 32 / 256, 256>>>(3200, 49 * 64, bias2, x, h2);

    // conv3: in=80, K=64, OUT=16, Cc=66*16=1056
    build_wcat_k<<<(80 * 1056 + 255) / 256, 256>>>(w3b, b3b, root3, 80, 64, 16);
    sgemm_k<<<dim3(9, 64), 256>>>(h2, 80, 1056);
    edge_msg16_k<<<NE * 16 / 256, 256>>>(1056, 65, 82 * NE);
    agg16_k<<<NN * 16 / 256, 256>>>(1056, 65 * 16, bias3);

    out_k<<<NN / 256, 256>>>(out);
}

// round 9
// speedup vs baseline: 1.1025x; 1.1025x over previous
#include <cuda_runtime.h>

#define NN 8192
#define NE 32768
#define NB 32
#define EB 1024

// ---------------- device scratch (no allocations allowed) ----------------
__device__ int   g_is64;
__device__ int   g_src[NE], g_dst[NE];
__device__ int   g_cnt[NN];
__device__ int   g_start[NN + 1];
__device__ float g_cntf[NN];
__device__ int   g_bhist[NB * NN];
__device__ int   g_perm[NE];
__device__ float g_m[147 * NE];            // m1_aug(33)|m2_aug(49)|m3_aug(65), column-major [k][e]
__device__ float g_W[80 * 3200];           // Wcat for current conv
__device__ float g_Q[(size_t)NN * 3200];   // Q = h @ Wcat (max ~105 MB)
__device__ float g_msg[NE * 64];
__device__ float g_h1[NN * 80];
__device__ float g_h2[NN * 80];
__device__ float g_d3[NN * 16];
__device__ float g_gum[NN * 16];

__device__ __forceinline__ float lrelu(float v) { return v >= 0.f ? v : 0.01f * v; }

// ---------------- tf32 helpers ----------------
__device__ __forceinline__ float tf32r(float a) {
    unsigned u;
    asm("cvt.rna.tf32.f32 %0, %1;" : "=r"(u) : "f"(a));
    return __uint_as_float(u);
}

__device__ __forceinline__ void mma_tf32(float* c, const unsigned* a, const unsigned* b) {
    asm("mma.sync.aligned.m16n8k8.row.col.f32.tf32.tf32.f32 "
        "{%0,%1,%2,%3}, {%4,%5,%6,%7}, {%8,%9}, {%0,%1,%2,%3};"
        : "+f"(c[0]), "+f"(c[1]), "+f"(c[2]), "+f"(c[3])
        : "r"(a[0]), "r"(a[1]), "r"(a[2]), "r"(a[3]), "r"(b[0]), "r"(b[1]));
}

// ---------------- edge_index dtype detection + conversion ----------------
__global__ void detect_k(const void* ei) {
    if (threadIdx.x == 0) {
        const long long* p = (const long long*)ei;
        int ok = 1;
        for (int i = 0; i < 64; i++) {
            long long v = p[i];
            if (v < 0 || v >= NN) ok = 0;
        }
        g_is64 = ok;
    }
}

__global__ void convert_k(const void* ei) {
    int e = blockIdx.x * 256 + threadIdx.x;
    if (e >= NE) return;
    if (g_is64) {
        const long long* p = (const long long*)ei;
        g_src[e] = (int)p[e];
        g_dst[e] = (int)p[NE + e];
    } else {
        const int* p = (const int*)ei;
        g_src[e] = p[e];
        g_dst[e] = p[NE + e];
    }
}

// ---------------- deterministic dst-CSR build ----------------
__global__ void zero_cnt_k() { g_cnt[blockIdx.x * 256 + threadIdx.x] = 0; }

__global__ void hist_k() {
    int e = blockIdx.x * 256 + threadIdx.x;
    atomicAdd(&g_cnt[g_dst[e]], 1);
}

__global__ __launch_bounds__(1024) void scan_k() {
    __shared__ int ps[1024];
    int t = threadIdx.x;
    int loc[8];
    int s = 0;
    for (int i = 0; i < 8; i++) { loc[i] = g_cnt[t * 8 + i]; s += loc[i]; }
    ps[t] = s;
    __syncthreads();
    for (int d = 1; d < 1024; d <<= 1) {
        int v = (t >= d) ? ps[t - d] : 0;
        __syncthreads();
        ps[t] += v;
        __syncthreads();
    }
    int run = (t > 0) ? ps[t - 1] : 0;
    for (int i = 0; i < 8; i++) {
        int n = t * 8 + i;
        g_start[n] = run;
        g_cntf[n]  = (float)(loc[i] > 1 ? loc[i] : 1);
        run += loc[i];
    }
    if (t == 1023) g_start[NN] = run;
}

__global__ __launch_bounds__(1024) void bhist_k() {
    __shared__ int h[NN];
    int t = threadIdx.x;
    for (int i = t; i < NN; i += 1024) h[i] = 0;
    __syncthreads();
    atomicAdd(&h[g_dst[blockIdx.x * EB + t]], 1);
    __syncthreads();
    for (int i = t; i < NN; i += 1024) g_bhist[blockIdx.x * NN + i] = h[i];
}

__global__ void colscan_k() {
    int n = blockIdx.x * 256 + threadIdx.x;
    if (n >= NN) return;
    int run = g_start[n];
#pragma unroll
    for (int b = 0; b < NB; b++) {
        int t = g_bhist[b * NN + n];
        g_bhist[b * NN + n] = run;
        run += t;
    }
}

__global__ __launch_bounds__(1024) void place_k() {
    __shared__ int d[EB];
    int t = threadIdx.x;
    int e = blockIdx.x * EB + t;
    d[t] = g_dst[e];
    __syncthreads();
    int myd = d[t];
    int rank = 0;
    for (int j = 0; j < EB; j++) {
        int v = d[j];
        if (j < t && v == myd) rank++;
    }
    g_perm[g_bhist[blockIdx.x * NN + myd] + rank] = e;
}

// ---------------- edge MLP layer 1 (all three convs) ----------------
__global__ __launch_bounds__(256) void edge_mlp_k(
    const float* __restrict__ ea,
    const float* __restrict__ w1a, const float* __restrict__ b1a,
    const float* __restrict__ w2a, const float* __restrict__ b2a,
    const float* __restrict__ w3a, const float* __restrict__ b3a)
{
    __shared__ float sw[2448];
    for (int i = threadIdx.x; i < 2448; i += 256) {
        float v;
        if      (i < 512)  v = w1a[i];
        else if (i < 544)  v = b1a[i - 512];
        else if (i < 1312) v = w2a[i - 544];
        else if (i < 1360) v = b2a[i - 1312];
        else if (i < 2384) v = w3a[i - 1360];
        else               v = b3a[i - 2384];
        sw[i] = v;
    }
    __syncthreads();
    int e = blockIdx.x * 256 + threadIdx.x;
    float a[16];
    const float4* ep = (const float4*)(ea + (size_t)e * 16);
    float4 q0 = ep[0], q1 = ep[1], q2 = ep[2], q3 = ep[3];
    a[0]=q0.x; a[1]=q0.y; a[2]=q0.z; a[3]=q0.w;
    a[4]=q1.x; a[5]=q1.y; a[6]=q1.z; a[7]=q1.w;
    a[8]=q2.x; a[9]=q2.y; a[10]=q2.z; a[11]=q2.w;
    a[12]=q3.x; a[13]=q3.y; a[14]=q3.z; a[15]=q3.w;

    for (int j = 0; j < 32; j++) {
        float s = sw[512 + j];
#pragma unroll
        for (int i = 0; i < 16; i++) s = fmaf(a[i], sw[i * 32 + j], s);
        g_m[(size_t)j * NE + e] = lrelu(s);
    }
    g_m[(size_t)32 * NE + e] = 1.0f;

    for (int j = 0; j < 48; j++) {
        float s = sw[1312 + j];
#pragma unroll
        for (int i = 0; i < 16; i++) s = fmaf(a[i], sw[544 + i * 48 + j], s);
        g_m[(size_t)(33 + j) * NE + e] = lrelu(s);
    }
    g_m[(size_t)81 * NE + e] = 1.0f;

    for (int j = 0; j < 64; j++) {
        float s = sw[2384 + j];
#pragma unroll
        for (int i = 0; i < 16; i++) s = fmaf(a[i], sw[1360 + i * 64 + j], s);
        g_m[(size_t)(82 + j) * NE + e] = lrelu(s);
    }
    g_m[(size_t)146 * NE + e] = 1.0f;
}

// ---------------- Wcat = [wb blocks | bias block | root block] ----------------
__global__ void build_wcat_k(const float* __restrict__ wb, const float* __restrict__ bb,
                             const float* __restrict__ root, int inC, int K, int OUT)
{
    int idx = blockIdx.x * 256 + threadIdx.x;
    int Cc = (K + 2) * OUT;
    if (idx >= inC * Cc) return;
    int i = idx / Cc, c = idx - i * Cc;
    int k = c / OUT, o = c - k * OUT;
    float v;
    if (k < K)       v = wb[(size_t)k * inC * OUT + i * OUT + o];
    else if (k == K) v = bb[i * OUT + o];
    else             v = root[i * OUT + o];
    g_W[idx] = v;
}

// ---------------- SGEMM (tf32 split, 4-term): g_Q = A[8192 x Kd] @ g_W[Kd x Cc] ----
// block tile 128x128, K-tile 16, 8 warps (4x2), warp tile 32x64, mma m16n8k8
__global__ __launch_bounds__(256, 2) void sgemm_k(const float* __restrict__ A, int Kd, int Cc)
{
    __shared__ float Ah[128][20], Al[128][20];
    __shared__ float Bh[16][136], Bl[16][136];
    int tid = threadIdx.x;
    int lane = tid & 31, warp = tid >> 5;
    int warpM = warp >> 1, warpN = warp & 1;
    int brow = blockIdx.y * 128, bcol = blockIdx.x * 128;
    int g = lane >> 2, t = lane & 3;

    float c[2][8][4];
#pragma unroll
    for (int mt = 0; mt < 2; mt++)
#pragma unroll
        for (int nt = 0; nt < 8; nt++)
#pragma unroll
            for (int r = 0; r < 4; r++) c[mt][nt][r] = 0.f;

    for (int k0 = 0; k0 < Kd; k0 += 16) {
        // load A tile [128 x 16], split hi/lo
        {
            int row = tid >> 1, c0 = (tid & 1) * 8;
            const float* ap = A + (size_t)(brow + row) * Kd + k0 + c0;
            float4 v0 = *(const float4*)ap;
            float4 v1 = *(const float4*)(ap + 4);
            float vv[8] = {v0.x, v0.y, v0.z, v0.w, v1.x, v1.y, v1.z, v1.w};
#pragma unroll
            for (int i = 0; i < 8; i++) {
                float hi = tf32r(vv[i]);
                Ah[row][c0 + i] = hi;
                Al[row][c0 + i] = tf32r(vv[i] - hi);
            }
        }
        // load B tile [16 x 128], split hi/lo (zero-pad cols >= Cc)
        {
            int row = tid >> 4, c0 = (tid & 15) * 8;
            const float* bp = g_W + (size_t)(k0 + row) * Cc + bcol + c0;
#pragma unroll
            for (int i = 0; i < 8; i++) {
                int col = bcol + c0 + i;
                float v = (col < Cc) ? bp[i] : 0.f;
                float hi = tf32r(v);
                Bh[row][c0 + i] = hi;
                Bl[row][c0 + i] = tf32r(v - hi);
            }
        }
        __syncthreads();
#pragma unroll
        for (int kk = 0; kk < 16; kk += 8) {
            unsigned ah[2][4], al[2][4];
#pragma unroll
            for (int mt = 0; mt < 2; mt++) {
                int r0 = warpM * 32 + mt * 16;
                ah[mt][0] = __float_as_uint(Ah[r0 + g][kk + t]);
                ah[mt][1] = __float_as_uint(Ah[r0 + g + 8][kk + t]);
                ah[mt][2] = __float_as_uint(Ah[r0 + g][kk + t + 4]);
                ah[mt][3] = __float_as_uint(Ah[r0 + g + 8][kk + t + 4]);
                al[mt][0] = __float_as_uint(Al[r0 + g][kk + t]);
                al[mt][1] = __float_as_uint(Al[r0 + g + 8][kk + t]);
                al[mt][2] = __float_as_uint(Al[r0 + g][kk + t + 4]);
                al[mt][3] = __float_as_uint(Al[r0 + g + 8][kk + t + 4]);
            }
#pragma unroll
            for (int nt = 0; nt < 8; nt++) {
                int n0 = warpN * 64 + nt * 8;
                unsigned bh[2], bl[2];
                bh[0] = __float_as_uint(Bh[kk + t][n0 + g]);
                bh[1] = __float_as_uint(Bh[kk + t + 4][n0 + g]);
                bl[0] = __float_as_uint(Bl[kk + t][n0 + g]);
                bl[1] = __float_as_uint(Bl[kk + t + 4][n0 + g]);
#pragma unroll
                for (int mt = 0; mt < 2; mt++) {
                    mma_tf32(c[mt][nt], al[mt], bl);
                    mma_tf32(c[mt][nt], al[mt], bh);
                    mma_tf32(c[mt][nt], ah[mt], bl);
                    mma_tf32(c[mt][nt], ah[mt], bh);
                }
            }
        }
        __syncthreads();
    }
#pragma unroll
    for (int mt = 0; mt < 2; mt++) {
#pragma unroll
        for (int nt = 0; nt < 8; nt++) {
            int row = brow + warpM * 32 + mt * 16 + g;
            int col = bcol + warpN * 64 + nt * 8 + 2 * t;
            if (col < Cc) {  // Cc even, col even -> col+1 < Cc too
                *(float2*)&g_Q[(size_t)row * Cc + col] =
                    make_float2(c[mt][nt][0], c[mt][nt][1]);
                *(float2*)&g_Q[(size_t)(row + 8) * Cc + col] =
                    make_float2(c[mt][nt][2], c[mt][nt][3]);
            }
        }
    }
}

// ---------------- per-edge message (32 threads/edge, float2) ----------------
__global__ __launch_bounds__(256) void edge_msg64_k(int Cc, int Kp1, int mOff)
{
    int t = blockIdx.x * 256 + threadIdx.x;   // NE*32 threads
    int e = t >> 5, lane = t & 31;
    int o = lane * 2;
    const float* mp = g_m + mOff + e;
    const float* q = g_Q + (size_t)g_src[e] * Cc + o;
    float a0 = 0.f, a1 = 0.f;
#pragma unroll 4
    for (int k = 0; k < Kp1; k++) {
        float mv = __ldg(mp + (size_t)k * NE);
        float2 qv = *(const float2*)(q + (size_t)k * 64);
        a0 = fmaf(mv, qv.x, a0);
        a1 = fmaf(mv, qv.y, a1);
    }
    *(float2*)&g_msg[(size_t)e * 64 + o] = make_float2(a0, a1);
}

__global__ __launch_bounds__(256) void edge_msg16_k(int Cc, int Kp1, int mOff)
{
    int t = blockIdx.x * 256 + threadIdx.x;
    int e = t >> 4, o = t & 15;
    const float* mp = g_m + mOff + e;
    const float* q = g_Q + (size_t)g_src[e] * Cc + o;
    float acc = 0.f;
#pragma unroll 4
    for (int k = 0; k < Kp1; k++)
        acc = fmaf(__ldg(mp + (size_t)k * NE), __ldg(q + (size_t)k * 16), acc);
    g_msg[t] = acc;
}

// ---------------- scatter-mean + root + bias + lrelu (+concat x) ----------------
__global__ __launch_bounds__(256) void agg64_k(int Cc, int rootCol,
    const float* __restrict__ bias, const float* __restrict__ x, float* __restrict__ hout)
{
    int gt = blockIdx.x * 256 + threadIdx.x;
    int node = gt >> 5, lane = gt & 31;
    int s = g_start[node], en = g_start[node + 1];
    float a0 = 0.f, a1 = 0.f;
    for (int j = s; j < en; j++) {
        int e = g_perm[j];
        const float* mr = g_msg + (size_t)e * 64;
        a0 += mr[lane];
        a1 += mr[lane + 32];
    }
    float cf = g_cntf[node];
    const float* qr = g_Q + (size_t)node * Cc + rootCol;
    hout[node * 80 + lane]      = lrelu(a0 / cf + qr[lane] + bias[lane]);
    hout[node * 80 + lane + 32] = lrelu(a1 / cf + qr[lane + 32] + bias[lane + 32]);
    if (lane < 16) hout[node * 80 + 64 + lane] = x[node * 16 + lane];
}

__global__ __launch_bounds__(256) void agg16_k(int Cc, int rootCol, const float* __restrict__ bias)
{
    int gt = blockIdx.x * 256 + threadIdx.x;
    int node = gt >> 4, lane = gt & 15;
    if (node >= NN) return;
    int s = g_start[node], en = g_start[node + 1];
    float a = 0.f;
    for (int j = s; j < en; j++)
        a += g_msg[(size_t)g_perm[j] * 16 + lane];
    g_d3[node * 16 + lane] =
        lrelu(a / g_cntf[node] + g_Q[(size_t)node * Cc + rootCol + lane] + bias[lane]);
}

// ---------------- JAX threefry2x32, PARTITIONABLE mode, bit_width=32 -----------
// bits[i] = out0 ^ out1 of threefry2x32((0,42), hi=0, lo=i)
__device__ __forceinline__ unsigned threefry_xor(unsigned x0, unsigned x1)
{
    const unsigned ks0 = 0u, ks1 = 42u, ks2 = 0u ^ 42u ^ 0x1BD11BDAu;
    unsigned v0 = x0 + ks0, v1 = x1 + ks1;
#define TFR(d) { v0 += v1; v1 = (v1 << d) | (v1 >> (32 - d)); v1 ^= v0; }
    TFR(13) TFR(15) TFR(26) TFR(6)   v0 += ks1; v1 += ks2 + 1u;
    TFR(17) TFR(29) TFR(16) TFR(24)  v0 += ks2; v1 += ks0 + 2u;
    TFR(13) TFR(15) TFR(26) TFR(6)   v0 += ks0; v1 += ks1 + 3u;
    TFR(17) TFR(29) TFR(16) TFR(24)  v0 += ks1; v1 += ks2 + 4u;
    TFR(13) TFR(15) TFR(26) TFR(6)   v0 += ks2; v1 += ks0 + 5u;
#undef TFR
    return v0 ^ v1;
}

__device__ __forceinline__ float bits_to_gumbel(unsigned b)
{
    float f = __uint_as_float((b >> 9) | 0x3F800000u) - 1.0f;  // [0,1)
    const float tiny = __uint_as_float(0x00800000u);           // FLT_MIN (normal)
    float u = fmaxf(f * 1.0f + tiny, tiny);
    return -logf(-logf(u));
}

__global__ void gumbel_k()
{
    int i = blockIdx.x * 256 + threadIdx.x;
    g_gum[i] = bits_to_gumbel(threefry_xor(0u, (unsigned)i));
}

// ---------------- final: one-hot(argmin(d3 + g)) ----------------
__global__ void out_k(float* __restrict__ out)
{
    int n = blockIdx.x * 256 + threadIdx.x;
    if (n >= NN) return;
    const float* d = g_d3 + n * 16;
    const float* g = g_gum + n * 16;
    float best = d[0] + g[0];
    int bi = 0;
#pragma unroll
    for (int c = 1; c < 16; c++) {
        float z = d[c] + g[c];
        if (z < best) { best = z; bi = c; }
    }
#pragma unroll
    for (int c = 0; c < 16; c++) out[n * 16 + c] = (c == bi) ? 1.0f : 0.0f;
}

// ---------------- host launch ----------------
extern "C" void kernel_launch(void* const* d_in, const int* in_sizes, int n_in,
                              void* d_out, int out_size)
{
    (void)in_sizes; (void)n_in; (void)out_size;
    const float* x     = (const float*)d_in[0];
    const void*  ei    = d_in[1];
    const float* ea    = (const float*)d_in[2];
    const float* w1a   = (const float*)d_in[3];
    const float* b1a   = (const float*)d_in[4];
    const float* w1b   = (const float*)d_in[5];
    const float* b1b   = (const float*)d_in[6];
    const float* root1 = (const float*)d_in[7];
    const float* bias1 = (const float*)d_in[8];
    const float* w2a   = (const float*)d_in[9];
    const float* b2a   = (const float*)d_in[10];
    const float* w2b   = (const float*)d_in[11];
    const float* b2b   = (const float*)d_in[12];
    const float* root2 = (const float*)d_in[13];
    const float* bias2 = (const float*)d_in[14];
    const float* w3a   = (const float*)d_in[15];
    const float* b3a   = (const float*)d_in[16];
    const float* w3b   = (const float*)d_in[17];
    const float* b3b   = (const float*)d_in[18];
    const float* root3 = (const float*)d_in[19];
    const float* bias3 = (const float*)d_in[20];
    float* out = (float*)d_out;

    float *h1, *h2;
    cudaGetSymbolAddress((void**)&h1, g_h1);
    cudaGetSymbolAddress((void**)&h2, g_h2);

    // heavy kernels early so ncu's capture window (skip ~5) lands on sgemm
    detect_k<<<1, 32>>>(ei);
    convert_k<<<NE / 256, 256>>>(ei);
    build_wcat_k<<<(16 * 2176 + 255) / 256, 256>>>(w1b, b1b, root1, 16, 32, 64);
    edge_mlp_k<<<NE / 256, 256>>>(ea, w1a, b1a, w2a, b2a, w3a, b3a);
    sgemm_k<<<dim3(17, 64), 256>>>(x, 16, 2176);        // conv1 Q
    edge_msg64_k<<<NE * 32 / 256, 256>>>(2176, 33, 0);

    // CSR build (needed before agg)
    zero_cnt_k<<<NN / 256, 256>>>();
    hist_k<<<NE / 256, 256>>>();
    scan_k<<<1, 1024>>>();
    bhist_k<<<NB, 1024>>>();
    colscan_k<<<NN / 256, 256>>>();
    place_k<<<NB, 1024>>>();
    gumbel_k<<<131072 / 256, 256>>>();

    agg64_k<<<NN * 32 / 256, 256>>>(2176, 33 * 64, bias1, x, h1);

    // conv2: in=80, K=48, OUT=64, Cc=50*64=3200
    build_wcat_k<<<(80 * 3200 + 255) / 256, 256>>>(w2b, b2b, root2, 80, 48, 64);
    sgemm_k<<<dim3(25, 64), 256>>>(h1, 80, 3200);
    edge_msg64_k<<<NE * 32 / 256, 256>>>(3200, 49, 33 * NE);
    agg64_k<<<NN * 32 / 256, 256>>>(3200, 49 * 64, bias2, x, h2);

    // conv3: in=80, K=64, OUT=16, Cc=66*16=1056
    build_wcat_k<<<(80 * 1056 + 255) / 256, 256>>>(w3b, b3b, root3, 80, 64, 16);
    sgemm_k<<<dim3(9, 64), 256>>>(h2, 80, 1056);
    edge_msg16_k<<<NE * 16 / 256, 256>>>(1056, 65, 82 * NE);
    agg16_k<<<NN * 16 / 256, 256>>>(1056, 65 * 16, bias3);

    out_k<<<NN / 256, 256>>>(out);
}